// round 4
// baseline (speedup 1.0000x reference)
#include <cuda_runtime.h>
#include <cstdint>

#define GRID   32
#define NCELL  (GRID*GRID*GRID)
#define BMAX   4
#define MMAX   4096
#define NMAX   16384
#define DOMAIN 4.5f
#define F_INF  __int_as_float(0x7f800000)

// ---------------- device scratch (allocation-free rule) ----------------
// points
__device__ int      g_cnt[BMAX][NCELL];
__device__ uint32_t g_tbl[BMAX][NCELL];      // start<<16 | cnt
__device__ int      g_ptcell[BMAX][MMAX];
__device__ float4   g_pts[BMAX][MMAX];       // cell-sorted (x,y,z,|p|^2) scaled
__device__ int      g_pidx[BMAX][MMAX];
// queries
__device__ int      g_cnt_q[BMAX][NCELL];
__device__ int      g_qcell[BMAX][NMAX];
__device__ int      g_qid[BMAX][NMAX];       // cell-sorted query indices

__device__ __forceinline__ float decode_scalar_f(const void* p) {
    int iv = *(const int*)p;
    if (iv >= -1000000 && iv <= 1000000) return (float)iv;
    return __int_as_float(iv);
}
__device__ __forceinline__ int clampi(int v, int lo, int hi) {
    return v < lo ? lo : (v > hi ? hi : v);
}
__device__ __forceinline__ int cell_of(float x, float y, float z) {
    const float invh = (float)GRID / (2.0f * DOMAIN);
    int cx = clampi((int)floorf((x + DOMAIN) * invh), 0, GRID - 1);
    int cy = clampi((int)floorf((y + DOMAIN) * invh), 0, GRID - 1);
    int cz = clampi((int)floorf((z + DOMAIN) * invh), 0, GRID - 1);
    return (cz * GRID + cy) * GRID + cx;
}

// ---------------- k1: zero both count arrays ----------------
__global__ void zero_kernel() {
    int total = BMAX * NCELL;
    for (int i = blockIdx.x * blockDim.x + threadIdx.x; i < total;
         i += gridDim.x * blockDim.x) {
        ((int*)g_cnt)[i] = 0;
        ((int*)g_cnt_q)[i] = 0;
    }
}

// ---------------- k2: bin sparse points ----------------
__global__ void bin_pts_kernel(const float* __restrict__ sxyz,
                               const void* __restrict__ rf_ptr, int M) {
    int gid = blockIdx.x * blockDim.x + threadIdx.x;
    if (gid >= BMAX * M) return;
    int b = gid / M, m = gid - b * M;
    float inv_sigma = 1.0f / (rf_ptr ? decode_scalar_f(rf_ptr) : 1.0f);
    const float* P = sxyz + (size_t)b * 3 * M;
    int c = cell_of(P[m] * inv_sigma, P[M + m] * inv_sigma, P[2 * M + m] * inv_sigma);
    g_ptcell[b][m] = c;
    atomicAdd(&g_cnt[b][c], 1);
}

// ---------------- k3: bin queries ----------------
__global__ void bin_q_kernel(const float* __restrict__ xyz,
                             const void* __restrict__ rf_ptr, int N) {
    int gid = blockIdx.x * blockDim.x + threadIdx.x;
    if (gid >= BMAX * N) return;
    int b = gid / N, n = gid - b * N;
    float inv_sigma = 1.0f / (rf_ptr ? decode_scalar_f(rf_ptr) : 1.0f);
    const float* Q = xyz + (size_t)b * 3 * N;
    int c = cell_of(Q[n] * inv_sigma, Q[N + n] * inv_sigma, Q[2 * N + n] * inv_sigma);
    g_qcell[b][n] = c;
    atomicAdd(&g_cnt_q[b][c], 1);
}

// ---------------- k4: exclusive scan, 1 block/(batch,table) ----------------
// thread handles 32 consecutive cells serially; block-scan of partials.
__global__ void scan_kernel() {
    __shared__ int sh[1024];
    int b = blockIdx.x;
    int which = blockIdx.y;                 // 0=points, 1=queries
    int* cnt = which ? &g_cnt_q[b][0] : &g_cnt[b][0];
    uint32_t* tbl = which ? nullptr : &g_tbl[b][0];

    const int C = NCELL / 1024;             // 32
    int t = threadIdx.x;
    int base = t * C;

    int sum = 0;
#pragma unroll
    for (int i = 0; i < C; i++) sum += cnt[base + i];
    sh[t] = sum;
    __syncthreads();
    for (int off = 1; off < 1024; off <<= 1) {
        int y = (t >= off) ? sh[t - off] : 0;
        __syncthreads();
        sh[t] += y;
        __syncthreads();
    }
    int run = sh[t] - sum;                  // exclusive offset
#pragma unroll
    for (int i = 0; i < C; i++) {
        int v = cnt[base + i];
        if (tbl) tbl[base + i] = ((uint32_t)run << 16) | (uint32_t)v;
        cnt[base + i] = run;                // scatter cursor
        run += v;
    }
}

// ---------------- k5: scatter points ----------------
__global__ void scatter_pts_kernel(const float* __restrict__ sxyz,
                                   const void* __restrict__ rf_ptr, int M) {
    int gid = blockIdx.x * blockDim.x + threadIdx.x;
    if (gid >= BMAX * M) return;
    int b = gid / M, m = gid - b * M;
    float inv_sigma = 1.0f / (rf_ptr ? decode_scalar_f(rf_ptr) : 1.0f);
    const float* P = sxyz + (size_t)b * 3 * M;
    float x = P[m] * inv_sigma;
    float y = P[M + m] * inv_sigma;
    float z = P[2 * M + m] * inv_sigma;
    float p2 = fmaf(x, x, fmaf(y, y, z * z));
    int pos = atomicAdd(&g_cnt[b][g_ptcell[b][m]], 1);
    g_pts[b][pos] = make_float4(x, y, z, p2);
    g_pidx[b][pos] = m;
}

// ---------------- k6: scatter query ids ----------------
__global__ void scatter_q_kernel(int N) {
    int gid = blockIdx.x * blockDim.x + threadIdx.x;
    if (gid >= BMAX * N) return;
    int b = gid / N, n = gid - b * N;
    int pos = atomicAdd(&g_cnt_q[b][g_qcell[b][n]], 1);
    g_qid[b][pos] = n;
}

// ---------------- k7: ring-search query kernel (cell-sorted order) ----------------
__global__ void __launch_bounds__(64) query_kernel(
    const float* __restrict__ xyz, const float* __restrict__ sflow,
    const void* __restrict__ rf_ptr, float* __restrict__ out, int N, int M)
{
    const int b = blockIdx.y;
    const int spos = blockIdx.x * blockDim.x + threadIdx.x;
    if (spos >= N) return;
    const int n = g_qid[b][spos];           // spatially-sorted query index

    const float inv_sigma = 1.0f / (rf_ptr ? decode_scalar_f(rf_ptr) : 1.0f);
    const float h    = (2.0f * DOMAIN) / (float)GRID;
    const float invh = 1.0f / h;

    const size_t qb = (size_t)b * 3 * N;
    const float qx = xyz[qb + n] * inv_sigma;
    const float qy = xyz[qb + N + n] * inv_sigma;
    const float qz = xyz[qb + 2 * N + n] * inv_sigma;
    const float q2 = fmaf(qx, qx, fmaf(qy, qy, qz * qz));
    const float m2x = -2.0f * qx, m2y = -2.0f * qy, m2z = -2.0f * qz;

    const int cx = clampi((int)floorf((qx + DOMAIN) * invh), 0, GRID - 1);
    const int cy = clampi((int)floorf((qy + DOMAIN) * invh), 0, GRID - 1);
    const int cz = clampi((int)floorf((qz + DOMAIN) * invh), 0, GRID - 1);

    float b0 = F_INF, b1 = F_INF, b2 = F_INF, b3 = F_INF, b4 = F_INF;
    int   i0 = 0, i1 = 0, i2 = 0, i3 = 0, i4 = 0;

    const float MARGIN = 1.0f + 1e-5f;

    for (int r = 0; r < GRID; ++r) {
        if (r >= 2) {
            float bound = (float)(r - 1) * h;
            if (b4 * MARGIN <= bound * bound) break;
        }
        int zlo = cz - r < 0 ? 0 : cz - r, zhi = cz + r > GRID - 1 ? GRID - 1 : cz + r;
        int ylo = cy - r < 0 ? 0 : cy - r, yhi = cy + r > GRID - 1 ? GRID - 1 : cy + r;
        int xlo = cx - r < 0 ? 0 : cx - r, xhi = cx + r > GRID - 1 ? GRID - 1 : cx + r;
        for (int z = zlo; z <= zhi; ++z) {
            int az = z - cz; az = az < 0 ? -az : az;
            for (int y = ylo; y <= yhi; ++y) {
                int ay = y - cy; ay = ay < 0 ? -ay : ay;
                int am = az > ay ? az : ay;
                for (int x = xlo; x <= xhi; ++x) {
                    int ax = x - cx; ax = ax < 0 ? -ax : ax;
                    int ch = am > ax ? am : ax;
                    if (ch != r) continue;

                    float lox = fmaf((float)x, h, -DOMAIN), hix = lox + h;
                    float loy = fmaf((float)y, h, -DOMAIN), hiy = loy + h;
                    float loz = fmaf((float)z, h, -DOMAIN), hiz = loz + h;
                    float dx = fmaxf(lox - qx, fmaxf(qx - hix, 0.0f));
                    float dy = fmaxf(loy - qy, fmaxf(qy - hiy, 0.0f));
                    float dz = fmaxf(loz - qz, fmaxf(qz - hiz, 0.0f));
                    float md2 = fmaf(dx, dx, fmaf(dy, dy, dz * dz));
                    if (md2 > b4 * MARGIN) continue;

                    uint32_t tbl = g_tbl[b][(z * GRID + y) * GRID + x];
                    int cnt = (int)(tbl & 0xFFFFu);
                    int st  = (int)(tbl >> 16);
                    for (int t = 0; t < cnt; ++t) {
                        float4 p = g_pts[b][st + t];
                        float s = fmaf(m2x, p.x,
                                  fmaf(m2y, p.y,
                                  fmaf(m2z, p.z, q2 + p.w)));
                        if (s < b4) {
                            int j = g_pidx[b][st + t];
                            bool c3 = s < b3, c2 = s < b2, c1 = s < b1, c0 = s < b0;
                            b4 = c3 ? b3 : s;               i4 = c3 ? i3 : j;
                            b3 = c3 ? (c2 ? b2 : s) : b3;   i3 = c3 ? (c2 ? i2 : j) : i3;
                            b2 = c2 ? (c1 ? b1 : s) : b2;   i2 = c2 ? (c1 ? i1 : j) : i2;
                            b1 = c1 ? (c0 ? b0 : s) : b1;   i1 = c1 ? (c0 ? i0 : j) : i1;
                            b0 = c0 ? s : b0;               i0 = c0 ? j : i0;
                        }
                    }
                }
            }
        }
    }

    float d0 = sqrtf(fmaxf(b0, 1e-12f));
    float d1 = sqrtf(fmaxf(b1, 1e-12f));
    float d2 = sqrtf(fmaxf(b2, 1e-12f));
    float d3 = sqrtf(fmaxf(b3, 1e-12f));
    float d4 = sqrtf(fmaxf(b4, 1e-12f));

    float w0 = 1.0f;
    float w1 = __expf(d0 - d1);
    float w2 = __expf(d0 - d2);
    float w3 = __expf(d0 - d3);
    float w4 = __expf(d0 - d4);
    float inv = 1.0f / (w0 + w1 + w2 + w3 + w4);

    const float* FL = sflow + (size_t)b * 3 * M;
    float fx = w0 * FL[i0] + w1 * FL[i1] + w2 * FL[i2] + w3 * FL[i3] + w4 * FL[i4];
    float fy = w0 * FL[M + i0] + w1 * FL[M + i1] + w2 * FL[M + i2]
             + w3 * FL[M + i3] + w4 * FL[M + i4];
    float fz = w0 * FL[2*M + i0] + w1 * FL[2*M + i1] + w2 * FL[2*M + i2]
             + w3 * FL[2*M + i3] + w4 * FL[2*M + i4];

    out[qb + n]         = fx * inv;
    out[qb + N + n]     = fy * inv;
    out[qb + 2 * N + n] = fz * inv;
}

// ---------------- launch ----------------
extern "C" void kernel_launch(void* const* d_in, const int* in_sizes, int n_in,
                              void* d_out, int out_size) {
    const float* xyz   = (const float*)d_in[0];
    const float* sxyz  = (const float*)d_in[1];
    const float* sflow = (const float*)d_in[2];
    const void*  rf    = (n_in > 3) ? d_in[3] : nullptr;
    float* out = (float*)d_out;

    const int B = BMAX;
    const int N = in_sizes[0] / (3 * B);   // 16384
    int M = in_sizes[1] / (3 * B);         // 4096
    if (M > MMAX) M = MMAX;

    zero_kernel<<<256, 256>>>();
    bin_pts_kernel<<<(B * M + 255) / 256, 256>>>(sxyz, rf, M);
    bin_q_kernel<<<(B * N + 255) / 256, 256>>>(xyz, rf, N);
    scan_kernel<<<dim3(B, 2), 1024>>>();
    scatter_pts_kernel<<<(B * M + 255) / 256, 256>>>(sxyz, rf, M);
    scatter_q_kernel<<<(B * N + 255) / 256, 256>>>(N);
    {
        dim3 blk(64, 1, 1);
        dim3 grd((N + 63) / 64, B, 1);
        query_kernel<<<grd, blk>>>(xyz, sflow, rf, out, N, M);
    }
}

// round 6
// speedup vs baseline: 1.7274x; 1.7274x over previous
#include <cuda_runtime.h>
#include <cstdint>

#define GRID   32
#define NCELL  (GRID*GRID*GRID)
#define BMAX   4
#define MMAX   4096
#define NMAX   16384
#define DOMAIN 4.5f
#define RMAX   4
#define F_INF  __int_as_float(0x7f800000)

// ---------------- device scratch (allocation-free rule) ----------------
__device__ int      g_cnt[BMAX][NCELL];
__device__ uint32_t g_tbl[BMAX][NCELL];      // start<<16 | cnt
__device__ int      g_ptcell[BMAX][MMAX];
__device__ float4   g_pts[BMAX][MMAX];       // cell-sorted (x,y,z,|p|^2) scaled
__device__ int      g_pidx[BMAX][MMAX];
__device__ int      g_cnt_q[BMAX][NCELL];
__device__ int      g_qcell[BMAX][NMAX];
__device__ int      g_qid[BMAX][NMAX];
__device__ int      g_ovf_cnt;
__device__ int      g_ovf[BMAX * NMAX];      // packed b<<20 | n

__device__ __forceinline__ float decode_scalar_f(const void* p) {
    int iv = *(const int*)p;
    if (iv >= -1000000 && iv <= 1000000) return (float)iv;
    return __int_as_float(iv);
}
__device__ __forceinline__ int clampi(int v, int lo, int hi) {
    return v < lo ? lo : (v > hi ? hi : v);
}
__device__ __forceinline__ int cell_of(float x, float y, float z) {
    const float invh = (float)GRID / (2.0f * DOMAIN);
    int cx = clampi((int)floorf((x + DOMAIN) * invh), 0, GRID - 1);
    int cy = clampi((int)floorf((y + DOMAIN) * invh), 0, GRID - 1);
    int cz = clampi((int)floorf((z + DOMAIN) * invh), 0, GRID - 1);
    return (cz * GRID + cy) * GRID + cx;
}

// ---------------- k1: zero ----------------
__global__ void zero_kernel() {
    int total = BMAX * NCELL;
    int tid = blockIdx.x * blockDim.x + threadIdx.x;
    if (tid == 0) g_ovf_cnt = 0;
    for (int i = tid; i < total; i += gridDim.x * blockDim.x) {
        ((int*)g_cnt)[i] = 0;
        ((int*)g_cnt_q)[i] = 0;
    }
}

// ---------------- k2/k3: binning ----------------
__global__ void bin_pts_kernel(const float* __restrict__ sxyz,
                               const void* __restrict__ rf_ptr, int M) {
    int gid = blockIdx.x * blockDim.x + threadIdx.x;
    if (gid >= BMAX * M) return;
    int b = gid / M, m = gid - b * M;
    float inv_sigma = 1.0f / (rf_ptr ? decode_scalar_f(rf_ptr) : 1.0f);
    const float* P = sxyz + (size_t)b * 3 * M;
    int c = cell_of(P[m] * inv_sigma, P[M + m] * inv_sigma, P[2 * M + m] * inv_sigma);
    g_ptcell[b][m] = c;
    atomicAdd(&g_cnt[b][c], 1);
}
__global__ void bin_q_kernel(const float* __restrict__ xyz,
                             const void* __restrict__ rf_ptr, int N) {
    int gid = blockIdx.x * blockDim.x + threadIdx.x;
    if (gid >= BMAX * N) return;
    int b = gid / N, n = gid - b * N;
    float inv_sigma = 1.0f / (rf_ptr ? decode_scalar_f(rf_ptr) : 1.0f);
    const float* Q = xyz + (size_t)b * 3 * N;
    int c = cell_of(Q[n] * inv_sigma, Q[N + n] * inv_sigma, Q[2 * N + n] * inv_sigma);
    g_qcell[b][n] = c;
    atomicAdd(&g_cnt_q[b][c], 1);
}

// ---------------- k4: exclusive scan (shuffle-based, 3 barriers) ----------------
__global__ void scan_kernel() {
    __shared__ int warp_part[32];
    int b = blockIdx.x;
    int which = blockIdx.y;
    int* cnt = which ? &g_cnt_q[b][0] : &g_cnt[b][0];
    uint32_t* tbl = which ? nullptr : &g_tbl[b][0];

    const int C = NCELL / 1024;                // 32 cells per thread
    int t = threadIdx.x, lane = t & 31, wid = t >> 5;
    int base = t * C;

    int sum = 0;
#pragma unroll
    for (int i = 0; i < C; i++) sum += cnt[base + i];

    // warp inclusive scan
    int sc = sum;
#pragma unroll
    for (int off = 1; off < 32; off <<= 1) {
        int y = __shfl_up_sync(0xFFFFFFFFu, sc, off);
        if (lane >= off) sc += y;
    }
    if (lane == 31) warp_part[wid] = sc;
    __syncthreads();
    if (wid == 0) {
        int w = warp_part[lane];
        int ws = w;
#pragma unroll
        for (int off = 1; off < 32; off <<= 1) {
            int y = __shfl_up_sync(0xFFFFFFFFu, ws, off);
            if (lane >= off) ws += y;
        }
        warp_part[lane] = ws - w;              // exclusive warp offsets
    }
    __syncthreads();

    int run = warp_part[wid] + sc - sum;       // exclusive offset of this thread
#pragma unroll
    for (int i = 0; i < C; i++) {
        int v = cnt[base + i];
        if (tbl) tbl[base + i] = ((uint32_t)run << 16) | (uint32_t)v;
        cnt[base + i] = run;                   // scatter cursor
        run += v;
    }
}

// ---------------- k5/k6: scatter ----------------
__global__ void scatter_pts_kernel(const float* __restrict__ sxyz,
                                   const void* __restrict__ rf_ptr, int M) {
    int gid = blockIdx.x * blockDim.x + threadIdx.x;
    if (gid >= BMAX * M) return;
    int b = gid / M, m = gid - b * M;
    float inv_sigma = 1.0f / (rf_ptr ? decode_scalar_f(rf_ptr) : 1.0f);
    const float* P = sxyz + (size_t)b * 3 * M;
    float x = P[m] * inv_sigma;
    float y = P[M + m] * inv_sigma;
    float z = P[2 * M + m] * inv_sigma;
    float p2 = fmaf(x, x, fmaf(y, y, z * z));
    int pos = atomicAdd(&g_cnt[b][g_ptcell[b][m]], 1);
    g_pts[b][pos] = make_float4(x, y, z, p2);
    g_pidx[b][pos] = m;
}
__global__ void scatter_q_kernel(int N) {
    int gid = blockIdx.x * blockDim.x + threadIdx.x;
    if (gid >= BMAX * N) return;
    int b = gid / N, n = gid - b * N;
    int pos = atomicAdd(&g_cnt_q[b][g_qcell[b][n]], 1);
    g_qid[b][pos] = n;
}

// shared finalize: softmax over -sqrt + flow gather
__device__ __forceinline__ void finalize_write(
    float b0, float b1, float b2, float b3, float b4,
    int i0, int i1, int i2, int i3, int i4,
    const float* __restrict__ FL, float* __restrict__ out,
    size_t qb, int n, int N, int M)
{
    float d0 = sqrtf(fmaxf(b0, 1e-12f));
    float d1 = sqrtf(fmaxf(b1, 1e-12f));
    float d2 = sqrtf(fmaxf(b2, 1e-12f));
    float d3 = sqrtf(fmaxf(b3, 1e-12f));
    float d4 = sqrtf(fmaxf(b4, 1e-12f));
    float w0 = 1.0f;
    float w1 = __expf(d0 - d1);
    float w2 = __expf(d0 - d2);
    float w3 = __expf(d0 - d3);
    float w4 = __expf(d0 - d4);
    float inv = 1.0f / (w0 + w1 + w2 + w3 + w4);
    float fx = w0*FL[i0] + w1*FL[i1] + w2*FL[i2] + w3*FL[i3] + w4*FL[i4];
    float fy = w0*FL[M+i0] + w1*FL[M+i1] + w2*FL[M+i2] + w3*FL[M+i3] + w4*FL[M+i4];
    float fz = w0*FL[2*M+i0] + w1*FL[2*M+i1] + w2*FL[2*M+i2] + w3*FL[2*M+i3] + w4*FL[2*M+i4];
    out[qb + n]         = fx * inv;
    out[qb + N + n]     = fy * inv;
    out[qb + 2 * N + n] = fz * inv;
}

// ---------------- k7: pass 1 — capped ring search ----------------
__global__ void __launch_bounds__(128) query_pass1(
    const float* __restrict__ xyz, const float* __restrict__ sflow,
    const void* __restrict__ rf_ptr, float* __restrict__ out, int N, int M)
{
    const int b = blockIdx.y;
    const int spos = blockIdx.x * blockDim.x + threadIdx.x;
    if (spos >= N) return;
    const int n = g_qid[b][spos];

    const float inv_sigma = 1.0f / (rf_ptr ? decode_scalar_f(rf_ptr) : 1.0f);
    const float h    = (2.0f * DOMAIN) / (float)GRID;
    const float invh = 1.0f / h;

    const size_t qb = (size_t)b * 3 * N;
    const float qx = xyz[qb + n] * inv_sigma;
    const float qy = xyz[qb + N + n] * inv_sigma;
    const float qz = xyz[qb + 2 * N + n] * inv_sigma;

    // out-of-domain query: cell-geometry bounds invalid -> brute force
    if (fabsf(qx) >= DOMAIN || fabsf(qy) >= DOMAIN || fabsf(qz) >= DOMAIN) {
        int slot = atomicAdd(&g_ovf_cnt, 1);
        g_ovf[slot] = (b << 20) | n;
        return;
    }

    const float q2 = fmaf(qx, qx, fmaf(qy, qy, qz * qz));
    const float m2x = -2.0f * qx, m2y = -2.0f * qy, m2z = -2.0f * qz;

    const int cx = clampi((int)floorf((qx + DOMAIN) * invh), 0, GRID - 1);
    const int cy = clampi((int)floorf((qy + DOMAIN) * invh), 0, GRID - 1);
    const int cz = clampi((int)floorf((qz + DOMAIN) * invh), 0, GRID - 1);

    float b0 = F_INF, b1 = F_INF, b2 = F_INF, b3 = F_INF, b4 = F_INF;
    int   i0 = 0, i1 = 0, i2 = 0, i3 = 0, i4 = 0;

    const float MARGIN = 1.0f + 1e-5f;
    bool done = false;

    for (int r = 0; r <= RMAX; ++r) {
        if (r >= 2) {
            float bound = (float)(r - 1) * h;
            if (b4 * MARGIN <= bound * bound) { done = true; break; }
        }
        int zlo = cz - r < 0 ? 0 : cz - r, zhi = cz + r > GRID - 1 ? GRID - 1 : cz + r;
        int ylo = cy - r < 0 ? 0 : cy - r, yhi = cy + r > GRID - 1 ? GRID - 1 : cy + r;
        int xlo = cx - r < 0 ? 0 : cx - r, xhi = cx + r > GRID - 1 ? GRID - 1 : cx + r;
        for (int z = zlo; z <= zhi; ++z) {
            int az = z - cz; az = az < 0 ? -az : az;
            for (int y = ylo; y <= yhi; ++y) {
                int ay = y - cy; ay = ay < 0 ? -ay : ay;
                int am = az > ay ? az : ay;
                for (int x = xlo; x <= xhi; ++x) {
                    int ax = x - cx; ax = ax < 0 ? -ax : ax;
                    int ch = am > ax ? am : ax;
                    if (ch != r) continue;

                    // cell box, outer faces of edge cells extended to inf
                    // (clamped out-of-domain points remain conservatively culled)
                    float lox = (x == 0)        ? -1e30f : fmaf((float)x, h, -DOMAIN);
                    float hix = (x == GRID - 1) ?  1e30f : fmaf((float)(x + 1), h, -DOMAIN);
                    float loy = (y == 0)        ? -1e30f : fmaf((float)y, h, -DOMAIN);
                    float hiy = (y == GRID - 1) ?  1e30f : fmaf((float)(y + 1), h, -DOMAIN);
                    float loz = (z == 0)        ? -1e30f : fmaf((float)z, h, -DOMAIN);
                    float hiz = (z == GRID - 1) ?  1e30f : fmaf((float)(z + 1), h, -DOMAIN);
                    float dx = fmaxf(lox - qx, fmaxf(qx - hix, 0.0f));
                    float dy = fmaxf(loy - qy, fmaxf(qy - hiy, 0.0f));
                    float dz = fmaxf(loz - qz, fmaxf(qz - hiz, 0.0f));
                    float md2 = fmaf(dx, dx, fmaf(dy, dy, dz * dz));
                    if (md2 > b4 * MARGIN) continue;

                    uint32_t tbl = g_tbl[b][(z * GRID + y) * GRID + x];
                    int cnt = (int)(tbl & 0xFFFFu);
                    int st  = (int)(tbl >> 16);
                    for (int t = 0; t < cnt; ++t) {
                        float4 p = g_pts[b][st + t];
                        float s = fmaf(m2x, p.x,
                                  fmaf(m2y, p.y,
                                  fmaf(m2z, p.z, q2 + p.w)));
                        if (s < b4) {
                            int j = g_pidx[b][st + t];
                            bool c3 = s < b3, c2 = s < b2, c1 = s < b1, c0 = s < b0;
                            b4 = c3 ? b3 : s;               i4 = c3 ? i3 : j;
                            b3 = c3 ? (c2 ? b2 : s) : b3;   i3 = c3 ? (c2 ? i2 : j) : i3;
                            b2 = c2 ? (c1 ? b1 : s) : b2;   i2 = c2 ? (c1 ? i1 : j) : i2;
                            b1 = c1 ? (c0 ? b0 : s) : b1;   i1 = c1 ? (c0 ? i0 : j) : i1;
                            b0 = c0 ? s : b0;               i0 = c0 ? j : i0;
                        }
                    }
                }
            }
        }
    }
    if (!done) {
        // completed rings 0..RMAX -> guarantee radius RMAX*h
        float bound = (float)RMAX * h;
        done = (b4 * MARGIN <= bound * bound);
    }
    if (!done) {
        int slot = atomicAdd(&g_ovf_cnt, 1);
        g_ovf[slot] = (b << 20) | n;
        return;
    }

    finalize_write(b0, b1, b2, b3, b4, i0, i1, i2, i3, i4,
                   sflow + (size_t)b * 3 * M, out, qb, n, N, M);
}

// ---------------- k8: pass 2 — warp-per-query exact brute force ----------------
__global__ void __launch_bounds__(128) query_pass2(
    const float* __restrict__ xyz, const float* __restrict__ sflow,
    const void* __restrict__ rf_ptr, float* __restrict__ out, int N, int M)
{
    const float inv_sigma = 1.0f / (rf_ptr ? decode_scalar_f(rf_ptr) : 1.0f);
    const int lane = threadIdx.x & 31;
    const int warp_global = (blockIdx.x * blockDim.x + threadIdx.x) >> 5;
    const int nwarps = (gridDim.x * blockDim.x) >> 5;
    const int total = g_ovf_cnt;
    const unsigned mask = 0xFFFFFFFFu;

    for (int q = warp_global; q < total; q += nwarps) {
        int packed = g_ovf[q];
        int b = packed >> 20;
        int n = packed & 0xFFFFF;
        size_t qb = (size_t)b * 3 * N;
        float qx = xyz[qb + n] * inv_sigma;
        float qy = xyz[qb + N + n] * inv_sigma;
        float qz = xyz[qb + 2 * N + n] * inv_sigma;
        float q2 = fmaf(qx, qx, fmaf(qy, qy, qz * qz));
        float m2x = -2.0f * qx, m2y = -2.0f * qy, m2z = -2.0f * qz;

        // per-lane sorted top-5 over strided points
        float b0 = F_INF, b1 = F_INF, b2 = F_INF, b3 = F_INF, b4 = F_INF;
        int   i0 = 0, i1 = 0, i2 = 0, i3 = 0, i4 = 0;
        for (int t = lane; t < M; t += 32) {
            float4 p = g_pts[b][t];
            float s = fmaf(m2x, p.x, fmaf(m2y, p.y, fmaf(m2z, p.z, q2 + p.w)));
            if (s < b4) {
                int j = g_pidx[b][t];
                bool c3 = s < b3, c2 = s < b2, c1 = s < b1, c0 = s < b0;
                b4 = c3 ? b3 : s;               i4 = c3 ? i3 : j;
                b3 = c3 ? (c2 ? b2 : s) : b3;   i3 = c3 ? (c2 ? i2 : j) : i3;
                b2 = c2 ? (c1 ? b1 : s) : b2;   i2 = c2 ? (c1 ? i1 : j) : i2;
                b1 = c1 ? (c0 ? b0 : s) : b1;   i1 = c1 ? (c0 ? i0 : j) : i1;
                b0 = c0 ? s : b0;               i0 = c0 ? j : i0;
            }
        }

        // 5-round warp merge: extract global min each round
        float rs[5]; int ri[5];
#pragma unroll
        for (int k = 0; k < 5; ++k) {
            float v = b0; int l = lane;
#pragma unroll
            for (int off = 16; off; off >>= 1) {
                float ov = __shfl_down_sync(mask, v, off);
                int   ol = __shfl_down_sync(mask, l, off);
                if (ov < v) { v = ov; l = ol; }
            }
            v = __shfl_sync(mask, v, 0);
            l = __shfl_sync(mask, l, 0);
            int gid = __shfl_sync(mask, i0, l);
            rs[k] = v; ri[k] = gid;
            if (lane == l) {
                b0 = b1; i0 = i1; b1 = b2; i1 = i2;
                b2 = b3; i2 = i3; b3 = b4; i3 = i4; b4 = F_INF;
            }
        }

        if (lane == 0) {
            finalize_write(rs[0], rs[1], rs[2], rs[3], rs[4],
                           ri[0], ri[1], ri[2], ri[3], ri[4],
                           sflow + (size_t)b * 3 * M, out, qb, n, N, M);
        }
    }
}

// ---------------- launch ----------------
extern "C" void kernel_launch(void* const* d_in, const int* in_sizes, int n_in,
                              void* d_out, int out_size) {
    const float* xyz   = (const float*)d_in[0];
    const float* sxyz  = (const float*)d_in[1];
    const float* sflow = (const float*)d_in[2];
    const void*  rf    = (n_in > 3) ? d_in[3] : nullptr;
    float* out = (float*)d_out;

    const int B = BMAX;
    const int N = in_sizes[0] / (3 * B);   // 16384
    int M = in_sizes[1] / (3 * B);         // 4096
    if (M > MMAX) M = MMAX;

    zero_kernel<<<256, 256>>>();
    bin_pts_kernel<<<(B * M + 255) / 256, 256>>>(sxyz, rf, M);
    bin_q_kernel<<<(B * N + 255) / 256, 256>>>(xyz, rf, N);
    scan_kernel<<<dim3(B, 2), 1024>>>();
    scatter_pts_kernel<<<(B * M + 255) / 256, 256>>>(sxyz, rf, M);
    scatter_q_kernel<<<(B * N + 255) / 256, 256>>>(N);
    {
        dim3 blk(128, 1, 1);
        dim3 grd((N + 127) / 128, B, 1);
        query_pass1<<<grd, blk>>>(xyz, sflow, rf, out, N, M);
    }
    query_pass2<<<592, 128>>>(xyz, sflow, rf, out, N, M);
}

// round 9
// speedup vs baseline: 2.0028x; 1.1594x over previous
#include <cuda_runtime.h>
#include <cstdint>

#define GRID    32
#define NCELL   (GRID*GRID*GRID)
#define BMAX    4
#define MMAX    4096
#define NMAX    16384
#define DOMAIN  4.5f
#define RMAX    4
#define CHUNK   512                      // cells per scan-A block
#define NCHUNKS ((BMAX*NCELL)/CHUNK)     // 256
#define CPB     (NCELL/CHUNK)            // 64 chunks per batch
#define F_INF   __int_as_float(0x7f800000)

// ---------------- device scratch (allocation-free rule) ----------------
__device__ int      g_cnt[BMAX][NCELL];      // cursors
__device__ uint32_t g_tbl[BMAX][NCELL];      // start<<16 | cnt
__device__ int      g_ptcell[BMAX][MMAX];
__device__ float4   g_pts[BMAX][MMAX];       // cell-sorted (x,y,z,|p|^2) scaled
__device__ int      g_pidx[BMAX][MMAX];
__device__ int      g_part[NCHUNKS];         // per-chunk totals
__device__ int      g_chunkoff[NCHUNKS];     // per-chunk exclusive offsets (per batch)
__device__ int      g_ovf_cnt;
__device__ int      g_ovf[BMAX * NMAX];      // packed b<<20 | n

__device__ __forceinline__ float decode_scalar_f(const void* p) {
    int iv = *(const int*)p;
    if (iv >= -1000000 && iv <= 1000000) return (float)iv;
    return __int_as_float(iv);
}
__device__ __forceinline__ int clampi(int v, int lo, int hi) {
    return v < lo ? lo : (v > hi ? hi : v);
}
__device__ __forceinline__ int cell_of(float x, float y, float z) {
    const float invh = (float)GRID / (2.0f * DOMAIN);
    int cx = clampi((int)floorf((x + DOMAIN) * invh), 0, GRID - 1);
    int cy = clampi((int)floorf((y + DOMAIN) * invh), 0, GRID - 1);
    int cz = clampi((int)floorf((z + DOMAIN) * invh), 0, GRID - 1);
    return (cz * GRID + cy) * GRID + cx;
}

// ---------------- k1: zero (512 blocks) ----------------
__global__ void zero_kernel() {
    int tid = blockIdx.x * blockDim.x + threadIdx.x;
    if (tid == 0) g_ovf_cnt = 0;
    if (tid < BMAX * NCELL) ((int*)g_cnt)[tid] = 0;
}

// ---------------- k2: bin sparse points (256 blocks x 64) ----------------
__global__ void bin_pts_kernel(const float* __restrict__ sxyz,
                               const void* __restrict__ rf_ptr, int M) {
    int gid = blockIdx.x * blockDim.x + threadIdx.x;
    if (gid >= BMAX * M) return;
    int b = gid / M, m = gid - b * M;
    float inv_sigma = 1.0f / (rf_ptr ? decode_scalar_f(rf_ptr) : 1.0f);
    const float* P = sxyz + (size_t)b * 3 * M;
    int c = cell_of(P[m] * inv_sigma, P[M + m] * inv_sigma, P[2 * M + m] * inv_sigma);
    g_ptcell[b][m] = c;
    atomicAdd(&g_cnt[b][c], 1);
}

// ---------------- k3: scan stage A — local block scans (256 blocks x 256) ----------------
__global__ void scanA_kernel() {
    __shared__ int wp[8];
    const int* cnt_flat = (const int*)g_cnt;
    uint32_t* tbl_flat = (uint32_t*)g_tbl;

    int t = threadIdx.x, lane = t & 31, wid = t >> 5;
    int base = blockIdx.x * CHUNK;          // flattened cell index

    int c0 = cnt_flat[base + 2 * t];
    int c1 = cnt_flat[base + 2 * t + 1];
    int s = c0 + c1;

    int sc = s;
#pragma unroll
    for (int off = 1; off < 32; off <<= 1) {
        int y = __shfl_up_sync(0xFFFFFFFFu, sc, off);
        if (lane >= off) sc += y;
    }
    if (lane == 31) wp[wid] = sc;
    __syncthreads();
    if (wid == 0 && lane < 8) {
        int w = wp[lane];
        int ws = w;
#pragma unroll
        for (int off = 1; off < 8; off <<= 1) {
            int y = __shfl_up_sync(0xFFu, ws, off);
            if (lane >= off) ws += y;
        }
        wp[lane] = ws - w;                  // exclusive warp offsets
    }
    __syncthreads();

    int excl = wp[wid] + sc - s;            // exclusive offset within chunk
    tbl_flat[base + 2 * t]     = ((uint32_t)excl << 16) | (uint32_t)c0;
    tbl_flat[base + 2 * t + 1] = ((uint32_t)(excl + c0) << 16) | (uint32_t)c1;
    if (t == blockDim.x - 1) g_part[blockIdx.x] = excl + c0 + c1;
}

// ---------------- k4: scan stage B — segmented scan of chunk totals (1 block) ----------------
__global__ void scanB_kernel() {
    __shared__ int part[NCHUNKS];
    int t = threadIdx.x;                    // 256 threads
    part[t] = g_part[t];
    __syncthreads();
    int segbase = (t / CPB) * CPB;          // batch boundary (64 chunks/batch)
    int run = 0;
    for (int i = segbase; i < t; ++i) run += part[i];
    g_chunkoff[t] = run;
}

// ---------------- k5: scan stage C — add chunk offsets (512 blocks x 256) ----------------
__global__ void scanC_kernel() {
    int e = blockIdx.x * blockDim.x + threadIdx.x;
    if (e >= BMAX * NCELL) return;
    uint32_t* tbl_flat = (uint32_t*)g_tbl;
    int* cnt_flat = (int*)g_cnt;
    uint32_t tbl = tbl_flat[e] + ((uint32_t)g_chunkoff[e / CHUNK] << 16);
    tbl_flat[e] = tbl;
    cnt_flat[e] = (int)(tbl >> 16);         // scatter cursor
}

// ---------------- k6: scatter points (256 blocks x 64) ----------------
__global__ void scatter_pts_kernel(const float* __restrict__ sxyz,
                                   const void* __restrict__ rf_ptr, int M) {
    int gid = blockIdx.x * blockDim.x + threadIdx.x;
    if (gid >= BMAX * M) return;
    int b = gid / M, m = gid - b * M;
    float inv_sigma = 1.0f / (rf_ptr ? decode_scalar_f(rf_ptr) : 1.0f);
    const float* P = sxyz + (size_t)b * 3 * M;
    float x = P[m] * inv_sigma;
    float y = P[M + m] * inv_sigma;
    float z = P[2 * M + m] * inv_sigma;
    float p2 = fmaf(x, x, fmaf(y, y, z * z));
    int pos = atomicAdd(&g_cnt[b][g_ptcell[b][m]], 1);
    g_pts[b][pos] = make_float4(x, y, z, p2);
    g_pidx[b][pos] = m;
}

// shared finalize: softmax over -sqrt + flow gather
__device__ __forceinline__ void finalize_write(
    float b0, float b1, float b2, float b3, float b4,
    int i0, int i1, int i2, int i3, int i4,
    const float* __restrict__ FL, float* __restrict__ out,
    size_t qb, int n, int N, int M)
{
    float d0 = sqrtf(fmaxf(b0, 1e-12f));
    float d1 = sqrtf(fmaxf(b1, 1e-12f));
    float d2 = sqrtf(fmaxf(b2, 1e-12f));
    float d3 = sqrtf(fmaxf(b3, 1e-12f));
    float d4 = sqrtf(fmaxf(b4, 1e-12f));
    float w0 = 1.0f;
    float w1 = __expf(d0 - d1);
    float w2 = __expf(d0 - d2);
    float w3 = __expf(d0 - d3);
    float w4 = __expf(d0 - d4);
    float inv = 1.0f / (w0 + w1 + w2 + w3 + w4);
    float fx = w0*FL[i0] + w1*FL[i1] + w2*FL[i2] + w3*FL[i3] + w4*FL[i4];
    float fy = w0*FL[M+i0] + w1*FL[M+i1] + w2*FL[M+i2] + w3*FL[M+i3] + w4*FL[M+i4];
    float fz = w0*FL[2*M+i0] + w1*FL[2*M+i1] + w2*FL[2*M+i2] + w3*FL[2*M+i3] + w4*FL[2*M+i4];
    out[qb + n]         = fx * inv;
    out[qb + N + n]     = fy * inv;
    out[qb + 2 * N + n] = fz * inv;
}

// ---------------- k7: pass 1 — capped ring search (natural query order) ----------------
__global__ void __launch_bounds__(128) query_pass1(
    const float* __restrict__ xyz, const float* __restrict__ sflow,
    const void* __restrict__ rf_ptr, float* __restrict__ out, int N, int M)
{
    const int b = blockIdx.y;
    const int n = blockIdx.x * blockDim.x + threadIdx.x;
    if (n >= N) return;

    const float inv_sigma = 1.0f / (rf_ptr ? decode_scalar_f(rf_ptr) : 1.0f);
    const float h    = (2.0f * DOMAIN) / (float)GRID;
    const float invh = 1.0f / h;

    const size_t qb = (size_t)b * 3 * N;
    const float qx = xyz[qb + n] * inv_sigma;
    const float qy = xyz[qb + N + n] * inv_sigma;
    const float qz = xyz[qb + 2 * N + n] * inv_sigma;

    // out-of-domain query: cell-geometry bounds invalid -> brute force
    if (fabsf(qx) >= DOMAIN || fabsf(qy) >= DOMAIN || fabsf(qz) >= DOMAIN) {
        int slot = atomicAdd(&g_ovf_cnt, 1);
        g_ovf[slot] = (b << 20) | n;
        return;
    }

    const float q2 = fmaf(qx, qx, fmaf(qy, qy, qz * qz));
    const float m2x = -2.0f * qx, m2y = -2.0f * qy, m2z = -2.0f * qz;

    const int cx = clampi((int)floorf((qx + DOMAIN) * invh), 0, GRID - 1);
    const int cy = clampi((int)floorf((qy + DOMAIN) * invh), 0, GRID - 1);
    const int cz = clampi((int)floorf((qz + DOMAIN) * invh), 0, GRID - 1);

    float b0 = F_INF, b1 = F_INF, b2 = F_INF, b3 = F_INF, b4 = F_INF;
    int   i0 = 0, i1 = 0, i2 = 0, i3 = 0, i4 = 0;

    const float MARGIN = 1.0f + 1e-5f;
    bool done = false;

    for (int r = 0; r <= RMAX; ++r) {
        if (r >= 2) {
            float bound = (float)(r - 1) * h;
            if (b4 * MARGIN <= bound * bound) { done = true; break; }
        }
        int zlo = cz - r < 0 ? 0 : cz - r, zhi = cz + r > GRID - 1 ? GRID - 1 : cz + r;
        int ylo = cy - r < 0 ? 0 : cy - r, yhi = cy + r > GRID - 1 ? GRID - 1 : cy + r;
        int xlo = cx - r < 0 ? 0 : cx - r, xhi = cx + r > GRID - 1 ? GRID - 1 : cx + r;
        for (int z = zlo; z <= zhi; ++z) {
            int az = z - cz; az = az < 0 ? -az : az;
            for (int y = ylo; y <= yhi; ++y) {
                int ay = y - cy; ay = ay < 0 ? -ay : ay;
                int am = az > ay ? az : ay;
                for (int x = xlo; x <= xhi; ++x) {
                    int ax = x - cx; ax = ax < 0 ? -ax : ax;
                    int ch = am > ax ? am : ax;
                    if (ch != r) continue;

                    // cell box; outer faces of edge cells extended to inf
                    float lox = (x == 0)        ? -1e30f : fmaf((float)x, h, -DOMAIN);
                    float hix = (x == GRID - 1) ?  1e30f : fmaf((float)(x + 1), h, -DOMAIN);
                    float loy = (y == 0)        ? -1e30f : fmaf((float)y, h, -DOMAIN);
                    float hiy = (y == GRID - 1) ?  1e30f : fmaf((float)(y + 1), h, -DOMAIN);
                    float loz = (z == 0)        ? -1e30f : fmaf((float)z, h, -DOMAIN);
                    float hiz = (z == GRID - 1) ?  1e30f : fmaf((float)(z + 1), h, -DOMAIN);
                    float dx = fmaxf(lox - qx, fmaxf(qx - hix, 0.0f));
                    float dy = fmaxf(loy - qy, fmaxf(qy - hiy, 0.0f));
                    float dz = fmaxf(loz - qz, fmaxf(qz - hiz, 0.0f));
                    float md2 = fmaf(dx, dx, fmaf(dy, dy, dz * dz));
                    if (md2 > b4 * MARGIN) continue;

                    uint32_t tbl = g_tbl[b][(z * GRID + y) * GRID + x];
                    int cnt = (int)(tbl & 0xFFFFu);
                    int st  = (int)(tbl >> 16);
                    for (int t = 0; t < cnt; ++t) {
                        float4 p = g_pts[b][st + t];
                        float s = fmaf(m2x, p.x,
                                  fmaf(m2y, p.y,
                                  fmaf(m2z, p.z, q2 + p.w)));
                        if (s < b4) {
                            int j = g_pidx[b][st + t];
                            bool c3 = s < b3, c2 = s < b2, c1 = s < b1, c0 = s < b0;
                            b4 = c3 ? b3 : s;               i4 = c3 ? i3 : j;
                            b3 = c3 ? (c2 ? b2 : s) : b3;   i3 = c3 ? (c2 ? i2 : j) : i3;
                            b2 = c2 ? (c1 ? b1 : s) : b2;   i2 = c2 ? (c1 ? i1 : j) : i2;
                            b1 = c1 ? (c0 ? b0 : s) : b1;   i1 = c1 ? (c0 ? i0 : j) : i1;
                            b0 = c0 ? s : b0;               i0 = c0 ? j : i0;
                        }
                    }
                }
            }
        }
    }
    if (!done) {
        float bound = (float)RMAX * h;
        done = (b4 * MARGIN <= bound * bound);
    }
    if (!done) {
        int slot = atomicAdd(&g_ovf_cnt, 1);
        g_ovf[slot] = (b << 20) | n;
        return;
    }

    finalize_write(b0, b1, b2, b3, b4, i0, i1, i2, i3, i4,
                   sflow + (size_t)b * 3 * M, out, qb, n, N, M);
}

// ---------------- k8: pass 2 — warp-per-query exact brute force ----------------
__global__ void __launch_bounds__(128) query_pass2(
    const float* __restrict__ xyz, const float* __restrict__ sflow,
    const void* __restrict__ rf_ptr, float* __restrict__ out, int N, int M)
{
    const float inv_sigma = 1.0f / (rf_ptr ? decode_scalar_f(rf_ptr) : 1.0f);
    const int lane = threadIdx.x & 31;
    const int warp_global = (blockIdx.x * blockDim.x + threadIdx.x) >> 5;
    const int nwarps = (gridDim.x * blockDim.x) >> 5;
    const int total = g_ovf_cnt;
    const unsigned mask = 0xFFFFFFFFu;

    for (int q = warp_global; q < total; q += nwarps) {
        int packed = g_ovf[q];
        int b = packed >> 20;
        int n = packed & 0xFFFFF;
        size_t qb = (size_t)b * 3 * N;
        float qx = xyz[qb + n] * inv_sigma;
        float qy = xyz[qb + N + n] * inv_sigma;
        float qz = xyz[qb + 2 * N + n] * inv_sigma;
        float q2 = fmaf(qx, qx, fmaf(qy, qy, qz * qz));
        float m2x = -2.0f * qx, m2y = -2.0f * qy, m2z = -2.0f * qz;

        float b0 = F_INF, b1 = F_INF, b2 = F_INF, b3 = F_INF, b4 = F_INF;
        int   i0 = 0, i1 = 0, i2 = 0, i3 = 0, i4 = 0;
        for (int t = lane; t < M; t += 32) {
            float4 p = g_pts[b][t];
            float s = fmaf(m2x, p.x, fmaf(m2y, p.y, fmaf(m2z, p.z, q2 + p.w)));
            if (s < b4) {
                int j = g_pidx[b][t];
                bool c3 = s < b3, c2 = s < b2, c1 = s < b1, c0 = s < b0;
                b4 = c3 ? b3 : s;               i4 = c3 ? i3 : j;
                b3 = c3 ? (c2 ? b2 : s) : b3;   i3 = c3 ? (c2 ? i2 : j) : i3;
                b2 = c2 ? (c1 ? b1 : s) : b2;   i2 = c2 ? (c1 ? i1 : j) : i2;
                b1 = c1 ? (c0 ? b0 : s) : b1;   i1 = c1 ? (c0 ? i0 : j) : i1;
                b0 = c0 ? s : b0;               i0 = c0 ? j : i0;
            }
        }

        float rs[5]; int ri[5];
#pragma unroll
        for (int k = 0; k < 5; ++k) {
            float v = b0; int l = lane;
#pragma unroll
            for (int off = 16; off; off >>= 1) {
                float ov = __shfl_down_sync(mask, v, off);
                int   ol = __shfl_down_sync(mask, l, off);
                if (ov < v) { v = ov; l = ol; }
            }
            v = __shfl_sync(mask, v, 0);
            l = __shfl_sync(mask, l, 0);
            int gid = __shfl_sync(mask, i0, l);
            rs[k] = v; ri[k] = gid;
            if (lane == l) {
                b0 = b1; i0 = i1; b1 = b2; i1 = i2;
                b2 = b3; i2 = i3; b3 = b4; i3 = i4; b4 = F_INF;
            }
        }

        if (lane == 0) {
            finalize_write(rs[0], rs[1], rs[2], rs[3], rs[4],
                           ri[0], ri[1], ri[2], ri[3], ri[4],
                           sflow + (size_t)b * 3 * M, out, qb, n, N, M);
        }
    }
}

// ---------------- launch ----------------
extern "C" void kernel_launch(void* const* d_in, const int* in_sizes, int n_in,
                              void* d_out, int out_size) {
    const float* xyz   = (const float*)d_in[0];
    const float* sxyz  = (const float*)d_in[1];
    const float* sflow = (const float*)d_in[2];
    const void*  rf    = (n_in > 3) ? d_in[3] : nullptr;
    float* out = (float*)d_out;

    const int B = BMAX;
    const int N = in_sizes[0] / (3 * B);   // 16384
    int M = in_sizes[1] / (3 * B);         // 4096
    if (M > MMAX) M = MMAX;

    zero_kernel<<<(BMAX * NCELL + 255) / 256, 256>>>();          // 512 CTAs
    bin_pts_kernel<<<(B * M + 63) / 64, 64>>>(sxyz, rf, M);      // 256 CTAs
    scanA_kernel<<<NCHUNKS, 256>>>();                            // 256 CTAs
    scanB_kernel<<<1, NCHUNKS>>>();                              // tiny
    scanC_kernel<<<(BMAX * NCELL + 255) / 256, 256>>>();         // 512 CTAs
    scatter_pts_kernel<<<(B * M + 63) / 64, 64>>>(sxyz, rf, M);  // 256 CTAs
    {
        dim3 blk(128, 1, 1);
        dim3 grd((N + 127) / 128, B, 1);                         // 512 CTAs
        query_pass1<<<grd, blk>>>(xyz, sflow, rf, out, N, M);
    }
    query_pass2<<<592, 128>>>(xyz, sflow, rf, out, N, M);
}